// round 2
// baseline (speedup 1.0000x reference)
#include <cuda_runtime.h>

// DWT_2D Haar: x (16,64,256,256) f32 -> (ll,lh,hl,hh) each (16,64,128,128),
// concatenated in d_out. Pure HBM-bound butterfly.
// R2: streaming cache hints (.cs) + 2 row-pairs per thread (MLP=8).

#define BCN   1024   // 16*64
#define HDIM  256
#define WDIM  256
#define OH    128
#define OW    128

__device__ __forceinline__ void butterfly4(float4 a4, float4 b4,
                                           float4& ll, float4& lh,
                                           float4& hl, float4& hh) {
    // a4 = row0 [a b a b], b4 = row1 [c d c d] for 2 output columns... actually
    // a4 holds 4 consecutive floats of row0 = (a0,b0,a1,b1), b4 = (c0,d0,c1,d1)
    float s0 = a4.x + a4.y, d0 = a4.x - a4.y;
    float s1 = a4.z + a4.w, d1 = a4.z - a4.w;
    float s2 = b4.x + b4.y, d2 = b4.x - b4.y;
    float s3 = b4.z + b4.w, d3 = b4.z - b4.w;
    ll.x = 0.5f * (s0 + s2);  lh.x = 0.5f * (d0 + d2);
    hl.x = 0.5f * (s0 - s2);  hh.x = 0.5f * (d0 - d2);
    ll.y = 0.5f * (s1 + s3);  lh.y = 0.5f * (d1 + d3);
    hl.y = 0.5f * (s1 - s3);  hh.y = 0.5f * (d1 - d3);
}

__global__ void __launch_bounds__(256)
dwt2d_haar_kernel(const float* __restrict__ x, float* __restrict__ out) {
    // tid = (bc << 11) | (i << 5) | g
    //   bc in [0,1024), i in [0,64) -> handles output rows i and i+64,
    //   g in [0,32) = group of 4 output cols
    unsigned tid = blockIdx.x * 256u + threadIdx.x;
    unsigned g  = tid & 31u;
    unsigned i  = (tid >> 5) & 63u;
    unsigned bc = tid >> 11;

    const float* baseA = x + (size_t)bc * (HDIM * WDIM) + (size_t)(2u * i) * WDIM + g * 8u;
    const float* baseB = baseA + (size_t)128u * WDIM;   // rows 2*(i+64), 2*(i+64)+1

    // 8 independent 128-bit streaming loads (MLP=8 per thread)
    float4 A0a = __ldcs((const float4*)baseA);
    float4 A0b = __ldcs((const float4*)(baseA + 4));
    float4 A1a = __ldcs((const float4*)(baseA + WDIM));
    float4 A1b = __ldcs((const float4*)(baseA + WDIM + 4));
    float4 B0a = __ldcs((const float4*)baseB);
    float4 B0b = __ldcs((const float4*)(baseB + 4));
    float4 B1a = __ldcs((const float4*)(baseB + WDIM));
    float4 B1b = __ldcs((const float4*)(baseB + WDIM + 4));

    float4 llA, lhA, hlA, hhA, llA2, lhA2, hlA2, hhA2;
    float4 t0, t1, t2, t3;

    // half A (row pair 2i, 2i+1): two float4 pairs -> 4 output cols per band
    butterfly4(A0a, A1a, llA, lhA, hlA, hhA);
    butterfly4(A0b, A1b, t0, t1, t2, t3);
    float4 llAo = make_float4(llA.x, llA.y, t0.x, t0.y);
    float4 lhAo = make_float4(lhA.x, lhA.y, t1.x, t1.y);
    float4 hlAo = make_float4(hlA.x, hlA.y, t2.x, t2.y);
    float4 hhAo = make_float4(hhA.x, hhA.y, t3.x, t3.y);

    // half B (row pair 2(i+64), 2(i+64)+1)
    butterfly4(B0a, B1a, llA2, lhA2, hlA2, hhA2);
    butterfly4(B0b, B1b, t0, t1, t2, t3);
    float4 llBo = make_float4(llA2.x, llA2.y, t0.x, t0.y);
    float4 lhBo = make_float4(lhA2.x, lhA2.y, t1.x, t1.y);
    float4 hlBo = make_float4(hlA2.x, hlA2.y, t2.x, t2.y);
    float4 hhBo = make_float4(hhA2.x, hhA2.y, t3.x, t3.y);

    const size_t band = (size_t)BCN * OH * OW;              // 16,777,216
    size_t oA = (size_t)bc * (OH * OW) + (size_t)i * OW + g * 4u;
    size_t oB = oA + (size_t)64u * OW;

    __stcs((float4*)(out + oA),            llAo);
    __stcs((float4*)(out + band + oA),     lhAo);
    __stcs((float4*)(out + 2 * band + oA), hlAo);
    __stcs((float4*)(out + 3 * band + oA), hhAo);
    __stcs((float4*)(out + oB),            llBo);
    __stcs((float4*)(out + band + oB),     lhBo);
    __stcs((float4*)(out + 2 * band + oB), hlBo);
    __stcs((float4*)(out + 3 * band + oB), hhBo);
}

extern "C" void kernel_launch(void* const* d_in, const int* in_sizes, int n_in,
                              void* d_out, int out_size) {
    const float* x = (const float*)d_in[0];
    float* out = (float*)d_out;
    // Total threads: 1024 * 64 * 32 = 2,097,152 -> 8192 blocks of 256
    dwt2d_haar_kernel<<<8192, 256>>>(x, out);
}

// round 3
// speedup vs baseline: 1.0086x; 1.0086x over previous
#include <cuda_runtime.h>

// DWT_2D Haar: x (16,64,256,256) f32 -> (ll,lh,hl,hh) each (16,64,128,128).
// R3: smem-staged, band-contiguous 4KB write bursts per block.
//
// Block = 256 threads, handles 8 output rows x 128 output cols of one (b,c):
//   reads  16 input rows  x 1KB = 16KB contiguous
//   writes 4 bands x 4KB contiguous bursts

#define BCN   1024
#define HDIM  256
#define WDIM  256
#define OH    128
#define OW    128

__global__ void __launch_bounds__(256)
dwt2d_haar_kernel(const float* __restrict__ x, float* __restrict__ out) {
    __shared__ float4 stage[4][256];   // [band][orow*32 + g]  -> 16KB

    unsigned b    = blockIdx.x;
    unsigned bc   = b >> 4;            // (b*c) slice, 0..1023
    unsigned rblk = b & 15u;           // 8-output-row block within slice, 0..15

    unsigned t    = threadIdx.x;
    unsigned g    = t & 31u;           // 4 output cols (8 input cols)
    unsigned orow = t >> 5;            // 0..7

    // ---- compute phase: butterfly on one row-pair segment ----
    unsigned irow = (rblk * 8u + orow) * 2u;
    const float* base = x + (size_t)bc * (HDIM * WDIM) + (size_t)irow * WDIM + g * 8u;

    float4 r0a = __ldcs((const float4*)base);
    float4 r0b = __ldcs((const float4*)(base + 4));
    float4 r1a = __ldcs((const float4*)(base + WDIM));
    float4 r1b = __ldcs((const float4*)(base + WDIM + 4));

    float t0[8] = {r0a.x, r0a.y, r0a.z, r0a.w, r0b.x, r0b.y, r0b.z, r0b.w};
    float t1[8] = {r1a.x, r1a.y, r1a.z, r1a.w, r1b.x, r1b.y, r1b.z, r1b.w};

    float llv[4], lhv[4], hlv[4], hhv[4];
#pragma unroll
    for (int k = 0; k < 4; ++k) {
        float a = t0[2 * k], bb = t0[2 * k + 1];
        float c = t1[2 * k], d  = t1[2 * k + 1];
        float s0 = a + bb, d0 = a - bb;
        float s1 = c + d,  d1 = c - d;
        llv[k] = 0.5f * (s0 + s1);
        lhv[k] = 0.5f * (d0 + d1);
        hlv[k] = 0.5f * (s0 - s1);
        hhv[k] = 0.5f * (d0 - d1);
    }

    unsigned e = orow * 32u + g;
    stage[0][e] = make_float4(llv[0], llv[1], llv[2], llv[3]);
    stage[1][e] = make_float4(lhv[0], lhv[1], lhv[2], lhv[3]);
    stage[2][e] = make_float4(hlv[0], hlv[1], hlv[2], hlv[3]);
    stage[3][e] = make_float4(hhv[0], hhv[1], hhv[2], hhv[3]);

    __syncthreads();

    // ---- write phase: warp w -> band w/2, half w%2; 4KB contiguous per band ----
    unsigned w    = t >> 5;            // warp id 0..7
    unsigned lane = t & 31u;
    unsigned band = w >> 1;            // 0..3
    unsigned half = w & 1u;            // 0..1

    const size_t bandstride = (size_t)BCN * OH * OW;  // elements
    // this block's chunk within the band: 8 rows x 128 cols, contiguous 4096B
    float4* dst = (float4*)(out + band * bandstride
                                + (size_t)bc * (OH * OW)
                                + (size_t)(rblk * 8u) * OW);

#pragma unroll
    for (int k = 0; k < 4; ++k) {
        unsigned idx = half * 128u + (unsigned)k * 32u + lane;  // float4 index, 0..255
        __stcs(dst + idx, stage[band][idx]);
    }
}

extern "C" void kernel_launch(void* const* d_in, const int* in_sizes, int n_in,
                              void* d_out, int out_size) {
    const float* x = (const float*)d_in[0];
    float* out = (float*)d_out;
    dwt2d_haar_kernel<<<16384, 256>>>(x, out);
}